// round 5
// baseline (speedup 1.0000x reference)
#include <cuda_runtime.h>

// ---------------------------------------------------------------------------
// DyNet2D R3: routing (pool+softmax) -> Winograd-transformed mixed weights
// U = G W G^T -> F(4x4,3x3) Winograd conv (4x fewer FMAs than direct).
// ---------------------------------------------------------------------------

#define HW (512 * 512)

__device__ float g_partial[1024];                  // (b*16+c)*4 + quarter
__device__ __align__(16) float g_u[16 * 16 * 16 * 36];  // [b][ic][oc][j36]

// ------------------------------ 1) pooling --------------------------------
__global__ void pool_kernel(const float* __restrict__ x) {
    const int blk = blockIdx.x;
    const int bc  = blk >> 2;
    const int q   = blk & 3;
    const float4* p = reinterpret_cast<const float4*>(x + (size_t)bc * HW + (size_t)q * 65536);
    float s = 0.0f;
    #pragma unroll 4
    for (int i = threadIdx.x; i < 16384; i += 256) {
        float4 v = p[i];
        s += (v.x + v.y) + (v.z + v.w);
    }
    #pragma unroll
    for (int o = 16; o > 0; o >>= 1) s += __shfl_down_sync(0xffffffffu, s, o);
    __shared__ float ws[8];
    if ((threadIdx.x & 31) == 0) ws[threadIdx.x >> 5] = s;
    __syncthreads();
    if (threadIdx.x == 0) {
        float t = 0.0f;
        #pragma unroll
        for (int i = 0; i < 8; i++) t += ws[i];
        g_partial[blk] = t;
    }
}

// --------------- 2) routing softmax + Winograd weight transform -----------
// U[b][ic][oc][6][6] = G * Wmix * G^T, Wmix = sum_e r[b][e] * We[oc][ic][3][3]
__global__ void mix_kernel(const float* __restrict__ w_experts,
                           const float* __restrict__ fc_w,
                           const float* __restrict__ fc_b) {
    __shared__ float pooled_s[256];
    __shared__ float r_s[16][3];
    const int tid = threadIdx.x;

    pooled_s[tid] = (g_partial[tid * 4 + 0] + g_partial[tid * 4 + 1] +
                     g_partial[tid * 4 + 2] + g_partial[tid * 4 + 3]) * (1.0f / (float)HW);
    __syncthreads();

    if (tid < 16) {
        float lg[3];
        #pragma unroll
        for (int e = 0; e < 3; e++) {
            float a = fc_b[e];
            #pragma unroll
            for (int c = 0; c < 16; c++) a += pooled_s[tid * 16 + c] * fc_w[e * 16 + c];
            lg[e] = a;
        }
        float m = fmaxf(lg[0], fmaxf(lg[1], lg[2]));
        float ex0 = expf(lg[0] - m), ex1 = expf(lg[1] - m), ex2 = expf(lg[2] - m);
        float inv = 1.0f / (ex0 + ex1 + ex2);
        r_s[tid][0] = ex0 * inv;
        r_s[tid][1] = ex1 * inv;
        r_s[tid][2] = ex2 * inv;
    }
    __syncthreads();

    // 4096 jobs: (b, ic, oc)
    for (int job = tid; job < 4096; job += 256) {
        int b  = job >> 8;
        int ic = (job >> 4) & 15;
        int oc = job & 15;

        float w[3][3];
        #pragma unroll
        for (int r = 0; r < 3; r++)
            #pragma unroll
            for (int c = 0; c < 3; c++) {
                float v = 0.0f;
                #pragma unroll
                for (int e = 0; e < 3; e++)
                    v += r_s[b][e] * w_experts[((e * 16 + oc) * 16 + ic) * 9 + r * 3 + c];
                w[r][c] = v;
            }

        // T = G * w  (6x3)
        float T[6][3];
        #pragma unroll
        for (int c = 0; c < 3; c++) {
            float w0 = w[0][c], w1 = w[1][c], w2 = w[2][c];
            T[0][c] = 0.25f * w0;
            T[1][c] = (-1.0f / 6.0f) * (w0 + w1 + w2);
            T[2][c] = (1.0f / 6.0f) * (-w0 + w1 - w2);
            T[3][c] = (1.0f / 24.0f) * w0 + (1.0f / 12.0f) * w1 + (1.0f / 6.0f) * w2;
            T[4][c] = (1.0f / 24.0f) * w0 - (1.0f / 12.0f) * w1 + (1.0f / 6.0f) * w2;
            T[5][c] = w2;
        }
        // U = T * G^T (6x6)
        float* up = g_u + (size_t)((b * 16 + ic) * 16 + oc) * 36;
        #pragma unroll
        for (int i = 0; i < 6; i++) {
            float t0 = T[i][0], t1 = T[i][1], t2 = T[i][2];
            up[i * 6 + 0] = 0.25f * t0;
            up[i * 6 + 1] = (-1.0f / 6.0f) * (t0 + t1 + t2);
            up[i * 6 + 2] = (1.0f / 6.0f) * (-t0 + t1 - t2);
            up[i * 6 + 3] = (1.0f / 24.0f) * t0 + (1.0f / 12.0f) * t1 + (1.0f / 6.0f) * t2;
            up[i * 6 + 4] = (1.0f / 24.0f) * t0 - (1.0f / 12.0f) * t1 + (1.0f / 6.0f) * t2;
            up[i * 6 + 5] = t2;
        }
    }
}

// ------------------------- 3) Winograd conv -------------------------------
// B^T applied to a 6-vector (14 ops)
__device__ __forceinline__ void btrans(float v0, float v1, float v2, float v3,
                                       float v4, float v5,
                                       float& o0, float& o1, float& o2,
                                       float& o3, float& o4, float& o5) {
    float a = v1 + v2;
    float b = v3 + v4;
    float c = v1 - v2;
    float e = v4 - v3;
    float f = v3 - v1;
    float g = v4 - v2;
    o0 = fmaf(4.0f, v0, fmaf(-5.0f, v2, v4));
    o1 = fmaf(-4.0f, a, b);
    o2 = fmaf(4.0f, c, e);
    o3 = fmaf(2.0f, f, g);
    o4 = fmaf(-2.0f, f, g);
    o5 = fmaf(4.0f, v1, fmaf(-5.0f, v3, v5));
}

// A^T applied to a 6-vector (10 ops)
__device__ __forceinline__ void atrans(float v0, float v1, float v2, float v3,
                                       float v4, float v5,
                                       float& o0, float& o1, float& o2, float& o3) {
    float s1 = v1 + v2;
    float s2 = v1 - v2;
    float s3 = v3 + v4;
    float s4 = v3 - v4;
    o0 = v0 + s1 + s3;
    o1 = fmaf(2.0f, s4, s2);
    o2 = fmaf(4.0f, s3, s1);
    o3 = fmaf(8.0f, s4, s2) + v5;
}

// SMEM layout (floats):
//   in_s : [16 ic][18 rows][68]        -> 19584
//   w_s  : [16 ic][16 oc][36]          ->  9216
//   bd_s : [8 icslot][64 tile][36]     -> 18432
// total 47232 floats = 188928 bytes
#define IN_S_OFF 0
#define W_S_OFF  19584
#define BD_S_OFF 28800

__global__ void __launch_bounds__(512, 1)
conv_kernel(const float* __restrict__ x, const float* __restrict__ bias,
            float* __restrict__ out) {
    extern __shared__ float smem[];
    float* in_s = smem + IN_S_OFF;
    float* w_s  = smem + W_S_OFF;
    float* bd_s = smem + BD_S_OFF;

    const int tid = threadIdx.x;
    const int b   = blockIdx.z;
    const int x0  = blockIdx.x * 64;
    const int y0  = blockIdx.y * 16;

    // ---- phase A: input tile + transformed weights ----
    const float* xb = x + (size_t)b * 16 * HW;
    for (int i = tid; i < 19008; i += 512) {       // 16 * 18 * 66
        int c   = i / 1188;
        int rem = i - c * 1188;
        int row = rem / 66;
        int col = rem - row * 66;
        int gy = y0 + row - 1; gy = gy < 0 ? -gy : (gy > 511 ? 1022 - gy : gy);
        int gx = x0 + col - 1; gx = gx < 0 ? -gx : (gx > 511 ? 1022 - gx : gx);
        in_s[c * 1224 + row * 68 + col] = xb[(c << 18) + (gy << 9) + gx];
    }
    {
        const float4* src = reinterpret_cast<const float4*>(g_u + (size_t)b * 9216);
        float4* dst = reinterpret_cast<float4*>(w_s);
        for (int i = tid; i < 2304; i += 512) dst[i] = src[i];
    }
    __syncthreads();

    // ---- per-thread job mapping ----
    const int oc   = tid & 7;          // phase C/D: oc and oc+8
    const int tile = tid >> 3;         // 0..63
    const int gx_t = tile & 15;
    const int gy_t = tile >> 4;

    float m0[36], m1[36];
    #pragma unroll
    for (int j = 0; j < 36; j++) { m0[j] = 0.0f; m1[j] = 0.0f; }

    #pragma unroll 1
    for (int chunk = 0; chunk < 2; chunk++) {
        // ---- phase B: input transform for 8 channels ----
        {
            const int icb   = chunk * 8 + (tid >> 6);
            const int btile = tid & 63;
            const int bgx   = btile & 15;
            const int bgy   = btile >> 4;
            const float* p = in_s + icb * 1224 + (4 * bgy) * 68 + 4 * bgx;

            float d[6][6];
            #pragma unroll
            for (int r = 0; r < 6; r++) {
                float4 a  = *reinterpret_cast<const float4*>(p + r * 68);
                float2 b2 = *reinterpret_cast<const float2*>(p + r * 68 + 4);
                d[r][0] = a.x; d[r][1] = a.y; d[r][2] = a.z; d[r][3] = a.w;
                d[r][4] = b2.x; d[r][5] = b2.y;
            }
            // columns (over rows)
            float t[6][6];
            #pragma unroll
            for (int c = 0; c < 6; c++)
                btrans(d[0][c], d[1][c], d[2][c], d[3][c], d[4][c], d[5][c],
                       t[0][c], t[1][c], t[2][c], t[3][c], t[4][c], t[5][c]);
            // rows (over cols)
            float bd[36];
            #pragma unroll
            for (int i = 0; i < 6; i++)
                btrans(t[i][0], t[i][1], t[i][2], t[i][3], t[i][4], t[i][5],
                       bd[i * 6 + 0], bd[i * 6 + 1], bd[i * 6 + 2],
                       bd[i * 6 + 3], bd[i * 6 + 4], bd[i * 6 + 5]);

            float* dst = bd_s + ((tid >> 6) * 64 + btile) * 36;
            #pragma unroll
            for (int q = 0; q < 9; q++)
                *reinterpret_cast<float4*>(dst + q * 4) =
                    make_float4(bd[q * 4 + 0], bd[q * 4 + 1], bd[q * 4 + 2], bd[q * 4 + 3]);
        }
        __syncthreads();

        // ---- phase C: elementwise accumulate over 8 channels ----
        {
            const float* bdp = bd_s + tile * 36;
            const float* wp0 = w_s + ((chunk * 8) * 16 + oc) * 36;
            #pragma unroll 1
            for (int ic = 0; ic < 8; ic++) {
                const float* wp1 = wp0 + 288;   // oc + 8
                #pragma unroll
                for (int jt = 0; jt < 3; jt++) {
                    float4 b0 = *reinterpret_cast<const float4*>(bdp + jt * 12 + 0);
                    float4 b1 = *reinterpret_cast<const float4*>(bdp + jt * 12 + 4);
                    float4 b2 = *reinterpret_cast<const float4*>(bdp + jt * 12 + 8);
                    float4 u0 = *reinterpret_cast<const float4*>(wp0 + jt * 12 + 0);
                    float4 u1 = *reinterpret_cast<const float4*>(wp0 + jt * 12 + 4);
                    float4 u2 = *reinterpret_cast<const float4*>(wp0 + jt * 12 + 8);
                    m0[jt*12+ 0] = fmaf(b0.x, u0.x, m0[jt*12+ 0]);
                    m0[jt*12+ 1] = fmaf(b0.y, u0.y, m0[jt*12+ 1]);
                    m0[jt*12+ 2] = fmaf(b0.z, u0.z, m0[jt*12+ 2]);
                    m0[jt*12+ 3] = fmaf(b0.w, u0.w, m0[jt*12+ 3]);
                    m0[jt*12+ 4] = fmaf(b1.x, u1.x, m0[jt*12+ 4]);
                    m0[jt*12+ 5] = fmaf(b1.y, u1.y, m0[jt*12+ 5]);
                    m0[jt*12+ 6] = fmaf(b1.z, u1.z, m0[jt*12+ 6]);
                    m0[jt*12+ 7] = fmaf(b1.w, u1.w, m0[jt*12+ 7]);
                    m0[jt*12+ 8] = fmaf(b2.x, u2.x, m0[jt*12+ 8]);
                    m0[jt*12+ 9] = fmaf(b2.y, u2.y, m0[jt*12+ 9]);
                    m0[jt*12+10] = fmaf(b2.z, u2.z, m0[jt*12+10]);
                    m0[jt*12+11] = fmaf(b2.w, u2.w, m0[jt*12+11]);
                    float4 v0 = *reinterpret_cast<const float4*>(wp1 + jt * 12 + 0);
                    float4 v1 = *reinterpret_cast<const float4*>(wp1 + jt * 12 + 4);
                    float4 v2 = *reinterpret_cast<const float4*>(wp1 + jt * 12 + 8);
                    m1[jt*12+ 0] = fmaf(b0.x, v0.x, m1[jt*12+ 0]);
                    m1[jt*12+ 1] = fmaf(b0.y, v0.y, m1[jt*12+ 1]);
                    m1[jt*12+ 2] = fmaf(b0.z, v0.z, m1[jt*12+ 2]);
                    m1[jt*12+ 3] = fmaf(b0.w, v0.w, m1[jt*12+ 3]);
                    m1[jt*12+ 4] = fmaf(b1.x, v1.x, m1[jt*12+ 4]);
                    m1[jt*12+ 5] = fmaf(b1.y, v1.y, m1[jt*12+ 5]);
                    m1[jt*12+ 6] = fmaf(b1.z, v1.z, m1[jt*12+ 6]);
                    m1[jt*12+ 7] = fmaf(b1.w, v1.w, m1[jt*12+ 7]);
                    m1[jt*12+ 8] = fmaf(b2.x, v2.x, m1[jt*12+ 8]);
                    m1[jt*12+ 9] = fmaf(b2.y, v2.y, m1[jt*12+ 9]);
                    m1[jt*12+10] = fmaf(b2.z, v2.z, m1[jt*12+10]);
                    m1[jt*12+11] = fmaf(b2.w, v2.w, m1[jt*12+11]);
                }
                bdp += 64 * 36;
                wp0 += 16 * 36;
            }
        }
        __syncthreads();
    }

    // ---- phase D: output transform A^T m A + bias, store ----
    const float bias0 = bias[oc];
    const float bias1 = bias[oc + 8];
    #pragma unroll
    for (int half = 0; half < 2; half++) {
        const float* m = half ? m1 : m0;
        const float bv = half ? bias1 : bias0;
        const int occ = half ? oc + 8 : oc;

        float t[4][6];
        #pragma unroll
        for (int j = 0; j < 6; j++)
            atrans(m[0 * 6 + j], m[1 * 6 + j], m[2 * 6 + j],
                   m[3 * 6 + j], m[4 * 6 + j], m[5 * 6 + j],
                   t[0][j], t[1][j], t[2][j], t[3][j]);

        float* op = out + ((size_t)(b * 16 + occ) << 18) +
                    ((size_t)(y0 + 4 * gy_t) << 9) + (x0 + 4 * gx_t);
        #pragma unroll
        for (int r = 0; r < 4; r++) {
            float o0, o1, o2, o3;
            atrans(t[r][0], t[r][1], t[r][2], t[r][3], t[r][4], t[r][5],
                   o0, o1, o2, o3);
            *reinterpret_cast<float4*>(op + ((size_t)r << 9)) =
                make_float4(o0 + bv, o1 + bv, o2 + bv, o3 + bv);
        }
    }
}

// ---------------------------------------------------------------------------
extern "C" void kernel_launch(void* const* d_in, const int* in_sizes, int n_in,
                              void* d_out, int out_size) {
    const float* x         = (const float*)d_in[0];
    const float* w_experts = (const float*)d_in[1];
    const float* bias      = (const float*)d_in[2];
    const float* fc_w      = (const float*)d_in[3];
    const float* fc_b      = (const float*)d_in[4];
    float* out = (float*)d_out;

    const int smem_bytes = 47232 * 4;   // 188928
    cudaFuncSetAttribute(conv_kernel, cudaFuncAttributeMaxDynamicSharedMemorySize, smem_bytes);

    pool_kernel<<<1024, 256>>>(x);
    mix_kernel<<<1, 256>>>(w_experts, fc_w, fc_b);
    conv_kernel<<<dim3(8, 32, 16), 512, smem_bytes>>>(x, bias, out);
}

// round 6
// speedup vs baseline: 1.3516x; 1.3516x over previous
#include <cuda_runtime.h>

// ---------------------------------------------------------------------------
// DyNet2D R5: routing -> U = G W G^T -> Winograd F(4x4,3x3) conv.
// Spill-free restructure of R4: 1 oc per thread (36 accs), CTA = 32x16 px
// subtile x2, 512 threads.
// ---------------------------------------------------------------------------

#define HW (512 * 512)

__device__ float g_partial[1024];                       // (b*16+c)*4 + quarter
__device__ __align__(16) float g_u[16 * 16 * 16 * 36];  // [b][ic][oc][36]

// ------------------------------ 1) pooling --------------------------------
__global__ void pool_kernel(const float* __restrict__ x) {
    const int blk = blockIdx.x;
    const int bc  = blk >> 2;
    const int q   = blk & 3;
    const float4* p = reinterpret_cast<const float4*>(x + (size_t)bc * HW + (size_t)q * 65536);
    float s = 0.0f;
    #pragma unroll 4
    for (int i = threadIdx.x; i < 16384; i += 256) {
        float4 v = p[i];
        s += (v.x + v.y) + (v.z + v.w);
    }
    #pragma unroll
    for (int o = 16; o > 0; o >>= 1) s += __shfl_down_sync(0xffffffffu, s, o);
    __shared__ float ws[8];
    if ((threadIdx.x & 31) == 0) ws[threadIdx.x >> 5] = s;
    __syncthreads();
    if (threadIdx.x == 0) {
        float t = 0.0f;
        #pragma unroll
        for (int i = 0; i < 8; i++) t += ws[i];
        g_partial[blk] = t;
    }
}

// --------------- 2) routing softmax + Winograd weight transform -----------
__global__ void mix_kernel(const float* __restrict__ w_experts,
                           const float* __restrict__ fc_w,
                           const float* __restrict__ fc_b) {
    __shared__ float pooled_s[256];
    __shared__ float r_s[16][3];
    const int tid = threadIdx.x;

    pooled_s[tid] = (g_partial[tid * 4 + 0] + g_partial[tid * 4 + 1] +
                     g_partial[tid * 4 + 2] + g_partial[tid * 4 + 3]) * (1.0f / (float)HW);
    __syncthreads();

    if (tid < 16) {
        float lg[3];
        #pragma unroll
        for (int e = 0; e < 3; e++) {
            float a = fc_b[e];
            #pragma unroll
            for (int c = 0; c < 16; c++) a += pooled_s[tid * 16 + c] * fc_w[e * 16 + c];
            lg[e] = a;
        }
        float m = fmaxf(lg[0], fmaxf(lg[1], lg[2]));
        float ex0 = expf(lg[0] - m), ex1 = expf(lg[1] - m), ex2 = expf(lg[2] - m);
        float inv = 1.0f / (ex0 + ex1 + ex2);
        r_s[tid][0] = ex0 * inv;
        r_s[tid][1] = ex1 * inv;
        r_s[tid][2] = ex2 * inv;
    }
    __syncthreads();

    for (int job = tid; job < 4096; job += 256) {
        int b  = job >> 8;
        int ic = (job >> 4) & 15;
        int oc = job & 15;

        float w[3][3];
        #pragma unroll
        for (int r = 0; r < 3; r++)
            #pragma unroll
            for (int c = 0; c < 3; c++) {
                float v = 0.0f;
                #pragma unroll
                for (int e = 0; e < 3; e++)
                    v += r_s[b][e] * w_experts[((e * 16 + oc) * 16 + ic) * 9 + r * 3 + c];
                w[r][c] = v;
            }

        float T[6][3];
        #pragma unroll
        for (int c = 0; c < 3; c++) {
            float w0 = w[0][c], w1 = w[1][c], w2 = w[2][c];
            T[0][c] = 0.25f * w0;
            T[1][c] = (-1.0f / 6.0f) * (w0 + w1 + w2);
            T[2][c] = (1.0f / 6.0f) * (-w0 + w1 - w2);
            T[3][c] = (1.0f / 24.0f) * w0 + (1.0f / 12.0f) * w1 + (1.0f / 6.0f) * w2;
            T[4][c] = (1.0f / 24.0f) * w0 - (1.0f / 12.0f) * w1 + (1.0f / 6.0f) * w2;
            T[5][c] = w2;
        }
        float* up = g_u + (size_t)((b * 16 + ic) * 16 + oc) * 36;
        #pragma unroll
        for (int i = 0; i < 6; i++) {
            float t0 = T[i][0], t1 = T[i][1], t2 = T[i][2];
            up[i * 6 + 0] = 0.25f * t0;
            up[i * 6 + 1] = (-1.0f / 6.0f) * (t0 + t1 + t2);
            up[i * 6 + 2] = (1.0f / 6.0f) * (-t0 + t1 - t2);
            up[i * 6 + 3] = (1.0f / 24.0f) * t0 + (1.0f / 12.0f) * t1 + (1.0f / 6.0f) * t2;
            up[i * 6 + 4] = (1.0f / 24.0f) * t0 - (1.0f / 12.0f) * t1 + (1.0f / 6.0f) * t2;
            up[i * 6 + 5] = t2;
        }
    }
}

// ------------------------- 3) Winograd conv -------------------------------
__device__ __forceinline__ void btrans(float v0, float v1, float v2, float v3,
                                       float v4, float v5,
                                       float& o0, float& o1, float& o2,
                                       float& o3, float& o4, float& o5) {
    float a = v1 + v2;
    float b = v3 + v4;
    float c = v1 - v2;
    float e = v4 - v3;
    float f = v3 - v1;
    float g = v4 - v2;
    o0 = fmaf(4.0f, v0, fmaf(-5.0f, v2, v4));
    o1 = fmaf(-4.0f, a, b);
    o2 = fmaf(4.0f, c, e);
    o3 = fmaf(2.0f, f, g);
    o4 = fmaf(-2.0f, f, g);
    o5 = fmaf(4.0f, v1, fmaf(-5.0f, v3, v5));
}

__device__ __forceinline__ void atrans(float v0, float v1, float v2, float v3,
                                       float v4, float v5,
                                       float& o0, float& o1, float& o2, float& o3) {
    float s1 = v1 + v2;
    float s2 = v1 - v2;
    float s3 = v3 + v4;
    float s4 = v3 - v4;
    o0 = v0 + s1 + s3;
    o1 = fmaf(2.0f, s4, s2);
    o2 = fmaf(4.0f, s3, s1);
    o3 = fmaf(8.0f, s4, s2) + v5;
}

// SMEM (floats):
//   w_s  : [16 ic][16 oc][36]          ->  9216   (offset 0)
//   in_s : [16 ic][18 rows][36 stride] -> 10368   (offset 9216, cols 0..33 used)
//   bd_s : [16 ic][32 tile][36]        -> 18432   (offset 19584)
// total 38016 floats = 152064 bytes
__global__ void __launch_bounds__(512, 1)
conv_kernel(const float* __restrict__ x, const float* __restrict__ bias,
            float* __restrict__ out) {
    extern __shared__ float smem[];
    float* w_s  = smem;
    float* in_s = smem + 9216;
    float* bd_s = smem + 19584;

    const int tid = threadIdx.x;
    const int b   = blockIdx.z;
    const int y0  = blockIdx.y * 16;
    const int x0b = blockIdx.x * 64;

    // transformed weights for this sample (persist across both subtiles)
    {
        const float4* src = reinterpret_cast<const float4*>(g_u + (size_t)b * 9216);
        float4* dst = reinterpret_cast<float4*>(w_s);
        for (int i = tid; i < 2304; i += 512) dst[i] = src[i];
    }

    // phase B mapping
    const int b_ic   = tid >> 5;           // 0..15
    const int b_tile = tid & 31;           // 0..31
    const int b_tx   = b_tile & 7;
    const int b_ty   = b_tile >> 3;
    // phase C/D mapping
    const int oc   = tid & 15;
    const int tile = tid >> 4;             // 0..31
    const int d_tx = tile & 7;
    const int d_ty = tile >> 3;

    const float bv = bias[oc];
    const float* xb = x + (size_t)b * 16 * HW;

    #pragma unroll 1
    for (int sub = 0; sub < 2; sub++) {
        const int x0 = x0b + sub * 32;

        // ---- phase A: input subtile (reflect halo) ----
        for (int i = tid; i < 9792; i += 512) {       // 16 * 18 * 34
            int c   = i / 612;
            int rem = i - c * 612;
            int row = rem / 34;
            int col = rem - row * 34;
            int gy = y0 + row - 1; gy = gy < 0 ? -gy : (gy > 511 ? 1022 - gy : gy);
            int gx = x0 + col - 1; gx = gx < 0 ? -gx : (gx > 511 ? 1022 - gx : gx);
            in_s[c * 648 + row * 36 + col] = xb[(c << 18) + (gy << 9) + gx];
        }
        __syncthreads();

        // ---- phase B: input transform, one (ic, tile) per thread ----
        {
            const float* p = in_s + b_ic * 648 + (4 * b_ty) * 36 + 4 * b_tx;
            float d[6][6];
            #pragma unroll
            for (int r = 0; r < 6; r++) {
                float4 a  = *reinterpret_cast<const float4*>(p + r * 36);
                float2 b2 = *reinterpret_cast<const float2*>(p + r * 36 + 4);
                d[r][0] = a.x; d[r][1] = a.y; d[r][2] = a.z; d[r][3] = a.w;
                d[r][4] = b2.x; d[r][5] = b2.y;
            }
            float t[6][6];
            #pragma unroll
            for (int c = 0; c < 6; c++)
                btrans(d[0][c], d[1][c], d[2][c], d[3][c], d[4][c], d[5][c],
                       t[0][c], t[1][c], t[2][c], t[3][c], t[4][c], t[5][c]);
            float bd[36];
            #pragma unroll
            for (int i = 0; i < 6; i++)
                btrans(t[i][0], t[i][1], t[i][2], t[i][3], t[i][4], t[i][5],
                       bd[i * 6 + 0], bd[i * 6 + 1], bd[i * 6 + 2],
                       bd[i * 6 + 3], bd[i * 6 + 4], bd[i * 6 + 5]);

            float* dst = bd_s + (b_ic * 32 + b_tile) * 36;
            #pragma unroll
            for (int q = 0; q < 9; q++)
                *reinterpret_cast<float4*>(dst + q * 4) =
                    make_float4(bd[q * 4 + 0], bd[q * 4 + 1], bd[q * 4 + 2], bd[q * 4 + 3]);
        }
        __syncthreads();

        // ---- phase C: accumulate m[36] for (tile, oc) over 16 ic ----
        float m[36];
        #pragma unroll
        for (int j = 0; j < 36; j++) m[j] = 0.0f;
        {
            const float* bdp = bd_s + tile * 36;
            const float* wp  = w_s + oc * 36;
            #pragma unroll 1
            for (int ic = 0; ic < 16; ic++) {
                #pragma unroll
                for (int q = 0; q < 9; q++) {
                    float4 bq = *reinterpret_cast<const float4*>(bdp + q * 4);
                    float4 uq = *reinterpret_cast<const float4*>(wp + q * 4);
                    m[q * 4 + 0] = fmaf(bq.x, uq.x, m[q * 4 + 0]);
                    m[q * 4 + 1] = fmaf(bq.y, uq.y, m[q * 4 + 1]);
                    m[q * 4 + 2] = fmaf(bq.z, uq.z, m[q * 4 + 2]);
                    m[q * 4 + 3] = fmaf(bq.w, uq.w, m[q * 4 + 3]);
                }
                bdp += 32 * 36;
                wp  += 16 * 36;
            }
        }
        __syncthreads();   // bd_s consumed; next iteration may rewrite

        // ---- phase D: A^T m A + bias, store ----
        {
            float t[4][6];
            #pragma unroll
            for (int j = 0; j < 6; j++)
                atrans(m[0 * 6 + j], m[1 * 6 + j], m[2 * 6 + j],
                       m[3 * 6 + j], m[4 * 6 + j], m[5 * 6 + j],
                       t[0][j], t[1][j], t[2][j], t[3][j]);

            float* op = out + ((size_t)(b * 16 + oc) << 18) +
                        ((size_t)(y0 + 4 * d_ty) << 9) + (x0 + 4 * d_tx);
            #pragma unroll
            for (int r = 0; r < 4; r++) {
                float o0, o1, o2, o3;
                atrans(t[r][0], t[r][1], t[r][2], t[r][3], t[r][4], t[r][5],
                       o0, o1, o2, o3);
                *reinterpret_cast<float4*>(op + ((size_t)r << 9)) =
                    make_float4(o0 + bv, o1 + bv, o2 + bv, o3 + bv);
            }
        }
    }
}

// ---------------------------------------------------------------------------
extern "C" void kernel_launch(void* const* d_in, const int* in_sizes, int n_in,
                              void* d_out, int out_size) {
    const float* x         = (const float*)d_in[0];
    const float* w_experts = (const float*)d_in[1];
    const float* bias      = (const float*)d_in[2];
    const float* fc_w      = (const float*)d_in[3];
    const float* fc_b      = (const float*)d_in[4];
    float* out = (float*)d_out;

    const int smem_bytes = 38016 * 4;   // 152064
    cudaFuncSetAttribute(conv_kernel, cudaFuncAttributeMaxDynamicSharedMemorySize, smem_bytes);

    pool_kernel<<<1024, 256>>>(x);
    mix_kernel<<<1, 256>>>(w_experts, fc_w, fc_b);
    conv_kernel<<<dim3(8, 32, 16), 512, smem_bytes>>>(x, bias, out);
}

// round 7
// speedup vs baseline: 1.6355x; 1.2100x over previous
#include <cuda_runtime.h>

// ---------------------------------------------------------------------------
// DyNet2D R6: Winograd F(4x4,3x3), LDS-wavefront-balanced.
//  - u layout [ic][q][oc][4]: warp reads 256B contiguous, conflict-free
//  - 2 tiles/thread (72 accs), CTA = 64x16 px, full 16-ic bd residency
//  - in_s/w_s share one SMEM union (disjoint lifetimes)
// ---------------------------------------------------------------------------

#define HW (512 * 512)

__device__ float g_partial[1024];                       // (b*16+c)*4 + quarter
__device__ __align__(16) float g_u[16 * 16 * 9 * 64];   // [b][ic][q][oc][4]

// ------------------------------ 1) pooling --------------------------------
__global__ void pool_kernel(const float* __restrict__ x) {
    const int blk = blockIdx.x;
    const int bc  = blk >> 2;
    const int q   = blk & 3;
    const float4* p = reinterpret_cast<const float4*>(x + (size_t)bc * HW + (size_t)q * 65536);
    float s = 0.0f;
    #pragma unroll 4
    for (int i = threadIdx.x; i < 16384; i += 256) {
        float4 v = p[i];
        s += (v.x + v.y) + (v.z + v.w);
    }
    #pragma unroll
    for (int o = 16; o > 0; o >>= 1) s += __shfl_down_sync(0xffffffffu, s, o);
    __shared__ float ws[8];
    if ((threadIdx.x & 31) == 0) ws[threadIdx.x >> 5] = s;
    __syncthreads();
    if (threadIdx.x == 0) {
        float t = 0.0f;
        #pragma unroll
        for (int i = 0; i < 8; i++) t += ws[i];
        g_partial[blk] = t;
    }
}

// --------------- 2) routing softmax + Winograd weight transform -----------
__global__ void mix_kernel(const float* __restrict__ w_experts,
                           const float* __restrict__ fc_w,
                           const float* __restrict__ fc_b) {
    __shared__ float pooled_s[256];
    __shared__ float r_s[16][3];
    const int tid = threadIdx.x;

    pooled_s[tid] = (g_partial[tid * 4 + 0] + g_partial[tid * 4 + 1] +
                     g_partial[tid * 4 + 2] + g_partial[tid * 4 + 3]) * (1.0f / (float)HW);
    __syncthreads();

    if (tid < 16) {
        float lg[3];
        #pragma unroll
        for (int e = 0; e < 3; e++) {
            float a = fc_b[e];
            #pragma unroll
            for (int c = 0; c < 16; c++) a += pooled_s[tid * 16 + c] * fc_w[e * 16 + c];
            lg[e] = a;
        }
        float m = fmaxf(lg[0], fmaxf(lg[1], lg[2]));
        float ex0 = expf(lg[0] - m), ex1 = expf(lg[1] - m), ex2 = expf(lg[2] - m);
        float inv = 1.0f / (ex0 + ex1 + ex2);
        r_s[tid][0] = ex0 * inv;
        r_s[tid][1] = ex1 * inv;
        r_s[tid][2] = ex2 * inv;
    }
    __syncthreads();

    for (int job = tid; job < 4096; job += 256) {
        int b  = job >> 8;
        int ic = (job >> 4) & 15;
        int oc = job & 15;

        float w[3][3];
        #pragma unroll
        for (int r = 0; r < 3; r++)
            #pragma unroll
            for (int c = 0; c < 3; c++) {
                float v = 0.0f;
                #pragma unroll
                for (int e = 0; e < 3; e++)
                    v += r_s[b][e] * w_experts[((e * 16 + oc) * 16 + ic) * 9 + r * 3 + c];
                w[r][c] = v;
            }

        float T[6][3];
        #pragma unroll
        for (int c = 0; c < 3; c++) {
            float w0 = w[0][c], w1 = w[1][c], w2 = w[2][c];
            T[0][c] = 0.25f * w0;
            T[1][c] = (-1.0f / 6.0f) * (w0 + w1 + w2);
            T[2][c] = (1.0f / 6.0f) * (-w0 + w1 - w2);
            T[3][c] = (1.0f / 24.0f) * w0 + (1.0f / 12.0f) * w1 + (1.0f / 6.0f) * w2;
            T[4][c] = (1.0f / 24.0f) * w0 - (1.0f / 12.0f) * w1 + (1.0f / 6.0f) * w2;
            T[5][c] = w2;
        }
        float u36[36];
        #pragma unroll
        for (int i = 0; i < 6; i++) {
            float t0 = T[i][0], t1 = T[i][1], t2 = T[i][2];
            u36[i * 6 + 0] = 0.25f * t0;
            u36[i * 6 + 1] = (-1.0f / 6.0f) * (t0 + t1 + t2);
            u36[i * 6 + 2] = (1.0f / 6.0f) * (-t0 + t1 - t2);
            u36[i * 6 + 3] = (1.0f / 24.0f) * t0 + (1.0f / 12.0f) * t1 + (1.0f / 6.0f) * t2;
            u36[i * 6 + 4] = (1.0f / 24.0f) * t0 - (1.0f / 12.0f) * t1 + (1.0f / 6.0f) * t2;
            u36[i * 6 + 5] = t2;
        }
        // scatter into [b][ic][q][oc][4]
        float* base = g_u + (size_t)(b * 16 + ic) * 576 + oc * 4;
        #pragma unroll
        for (int q = 0; q < 9; q++) {
            base[q * 64 + 0] = u36[q * 4 + 0];
            base[q * 64 + 1] = u36[q * 4 + 1];
            base[q * 64 + 2] = u36[q * 4 + 2];
            base[q * 64 + 3] = u36[q * 4 + 3];
        }
    }
}

// ------------------------- 3) Winograd conv -------------------------------
__device__ __forceinline__ void btrans(float v0, float v1, float v2, float v3,
                                       float v4, float v5,
                                       float& o0, float& o1, float& o2,
                                       float& o3, float& o4, float& o5) {
    float a = v1 + v2;
    float b = v3 + v4;
    float c = v1 - v2;
    float e = v4 - v3;
    float f = v3 - v1;
    float g = v4 - v2;
    o0 = fmaf(4.0f, v0, fmaf(-5.0f, v2, v4));
    o1 = fmaf(-4.0f, a, b);
    o2 = fmaf(4.0f, c, e);
    o3 = fmaf(2.0f, f, g);
    o4 = fmaf(-2.0f, f, g);
    o5 = fmaf(4.0f, v1, fmaf(-5.0f, v3, v5));
}

__device__ __forceinline__ void atrans(float v0, float v1, float v2, float v3,
                                       float v4, float v5,
                                       float& o0, float& o1, float& o2, float& o3) {
    float s1 = v1 + v2;
    float s2 = v1 - v2;
    float s3 = v3 + v4;
    float s4 = v3 - v4;
    o0 = v0 + s1 + s3;
    o1 = fmaf(2.0f, s4, s2);
    o2 = fmaf(4.0f, s3, s1);
    o3 = fmaf(8.0f, s4, s2) + v5;
}

// SMEM (floats):
//   bd_s  : [16 ic][64 tile][36]  -> 36864   (offset 0)
//   union : 19584                  (offset 36864)
//       phases A/B: in_s [16 ic][18 rows][68 stride] (cols 0..65 used)
//       phase  C  : w_s  [16 ic][9 q][16 oc][4] = 9216 (first part)
// total 56448 floats = 225792 bytes
__global__ void __launch_bounds__(512, 1)
conv_kernel(const float* __restrict__ x, const float* __restrict__ bias,
            float* __restrict__ out) {
    extern __shared__ float smem[];
    float* bd_s = smem;
    float* un_s = smem + 36864;      // in_s during A/B, w_s during C

    const int tid = threadIdx.x;
    const int b   = blockIdx.z;
    const int x0  = blockIdx.x * 64;
    const int y0  = blockIdx.y * 16;

    const int oc  = tid & 15;
    const int grp = tid >> 4;        // 0..31, handles tiles 2*grp, 2*grp+1

    const float bv = bias[oc];
    const float* xb = x + (size_t)b * 16 * HW;

    // ---- phase A: input tile 16ic x 18 x 66 (reflect halo), stride 68 ----
    for (int i = tid; i < 19008; i += 512) {
        int c   = i / 1188;                  // 18*66
        int rem = i - c * 1188;
        int row = rem / 66;
        int col = rem - row * 66;
        int gy = y0 + row - 1; gy = gy < 0 ? -gy : (gy > 511 ? 1022 - gy : gy);
        int gx = x0 + col - 1; gx = gx < 0 ? -gx : (gx > 511 ? 1022 - gx : gx);
        un_s[c * 1224 + row * 68 + col] = xb[(c << 18) + (gy << 9) + gx];
    }
    __syncthreads();

    // ---- phase B: input transform, 2 jobs/thread (16ic x 64 tiles) ----
    #pragma unroll
    for (int s = 0; s < 2; s++) {
        const int job  = tid + s * 512;
        const int b_ic = job >> 6;
        const int b_t  = job & 63;
        const int b_tx = b_t & 15;
        const int b_ty = b_t >> 4;
        const float* p = un_s + b_ic * 1224 + (4 * b_ty) * 68 + 4 * b_tx;

        float d[6][6];
        #pragma unroll
        for (int r = 0; r < 6; r++) {
            float4 a  = *reinterpret_cast<const float4*>(p + r * 68);
            float2 b2 = *reinterpret_cast<const float2*>(p + r * 68 + 4);
            d[r][0] = a.x; d[r][1] = a.y; d[r][2] = a.z; d[r][3] = a.w;
            d[r][4] = b2.x; d[r][5] = b2.y;
        }
        float t[6][6];
        #pragma unroll
        for (int c = 0; c < 6; c++)
            btrans(d[0][c], d[1][c], d[2][c], d[3][c], d[4][c], d[5][c],
                   t[0][c], t[1][c], t[2][c], t[3][c], t[4][c], t[5][c]);
        float bd[36];
        #pragma unroll
        for (int i = 0; i < 6; i++)
            btrans(t[i][0], t[i][1], t[i][2], t[i][3], t[i][4], t[i][5],
                   bd[i * 6 + 0], bd[i * 6 + 1], bd[i * 6 + 2],
                   bd[i * 6 + 3], bd[i * 6 + 4], bd[i * 6 + 5]);

        float* dst = bd_s + (b_ic * 64 + b_t) * 36;
        #pragma unroll
        for (int q = 0; q < 9; q++)
            *reinterpret_cast<float4*>(dst + q * 4) =
                make_float4(bd[q * 4 + 0], bd[q * 4 + 1], bd[q * 4 + 2], bd[q * 4 + 3]);
    }
    __syncthreads();

    // ---- load transformed weights into union (in_s dead now) ----
    {
        const float4* src = reinterpret_cast<const float4*>(g_u + (size_t)b * 9216);
        float4* dst = reinterpret_cast<float4*>(un_s);
        #pragma unroll
        for (int k = 0; k < 5; k++) {
            int i = tid + k * 512;
            if (i < 2304) dst[i] = src[i];
        }
    }
    __syncthreads();

    // ---- phase C: accumulate m[2][36] over 16 ic ----
    float m0[36], m1[36];
    #pragma unroll
    for (int j = 0; j < 36; j++) { m0[j] = 0.0f; m1[j] = 0.0f; }
    {
        const float* bdp0 = bd_s + (grp * 2 + 0) * 36;
        const float* bdp1 = bd_s + (grp * 2 + 1) * 36;
        const float* wq   = un_s + oc * 4;
        #pragma unroll 1
        for (int ic = 0; ic < 16; ic++) {
            #pragma unroll
            for (int q = 0; q < 9; q++) {
                float4 u  = *reinterpret_cast<const float4*>(wq + q * 64);
                float4 b0 = *reinterpret_cast<const float4*>(bdp0 + q * 4);
                float4 b1 = *reinterpret_cast<const float4*>(bdp1 + q * 4);
                m0[q*4+0] = fmaf(b0.x, u.x, m0[q*4+0]);
                m0[q*4+1] = fmaf(b0.y, u.y, m0[q*4+1]);
                m0[q*4+2] = fmaf(b0.z, u.z, m0[q*4+2]);
                m0[q*4+3] = fmaf(b0.w, u.w, m0[q*4+3]);
                m1[q*4+0] = fmaf(b1.x, u.x, m1[q*4+0]);
                m1[q*4+1] = fmaf(b1.y, u.y, m1[q*4+1]);
                m1[q*4+2] = fmaf(b1.z, u.z, m1[q*4+2]);
                m1[q*4+3] = fmaf(b1.w, u.w, m1[q*4+3]);
            }
            bdp0 += 64 * 36;
            bdp1 += 64 * 36;
            wq   += 576;
        }
    }

    // ---- phase D: A^T m A + bias for both tiles ----
    #pragma unroll
    for (int t2 = 0; t2 < 2; t2++) {
        const float* m = t2 ? m1 : m0;
        const int tile = grp * 2 + t2;
        const int tx = tile & 15;
        const int ty = tile >> 4;

        float t[4][6];
        #pragma unroll
        for (int j = 0; j < 6; j++)
            atrans(m[0 * 6 + j], m[1 * 6 + j], m[2 * 6 + j],
                   m[3 * 6 + j], m[4 * 6 + j], m[5 * 6 + j],
                   t[0][j], t[1][j], t[2][j], t[3][j]);

        float* op = out + ((size_t)(b * 16 + oc) << 18) +
                    ((size_t)(y0 + 4 * ty) << 9) + (x0 + 4 * tx);
        #pragma unroll
        for (int r = 0; r < 4; r++) {
            float o0, o1, o2, o3;
            atrans(t[r][0], t[r][1], t[r][2], t[r][3], t[r][4], t[r][5],
                   o0, o1, o2, o3);
            *reinterpret_cast<float4*>(op + ((size_t)r << 9)) =
                make_float4(o0 + bv, o1 + bv, o2 + bv, o3 + bv);
        }
    }
}

// ---------------------------------------------------------------------------
extern "C" void kernel_launch(void* const* d_in, const int* in_sizes, int n_in,
                              void* d_out, int out_size) {
    const float* x         = (const float*)d_in[0];
    const float* w_experts = (const float*)d_in[1];
    const float* bias      = (const float*)d_in[2];
    const float* fc_w      = (const float*)d_in[3];
    const float* fc_b      = (const float*)d_in[4];
    float* out = (float*)d_out;

    const int smem_bytes = 56448 * 4;   // 225792
    cudaFuncSetAttribute(conv_kernel, cudaFuncAttributeMaxDynamicSharedMemorySize, smem_bytes);

    pool_kernel<<<1024, 256>>>(x);
    mix_kernel<<<1, 256>>>(w_experts, fc_w, fc_b);
    conv_kernel<<<dim3(8, 32, 16), 512, smem_bytes>>>(x, bias, out);
}

// round 9
// speedup vs baseline: 1.8013x; 1.1014x over previous
#include <cuda_runtime.h>

// ---------------------------------------------------------------------------
// DyNet2D R7: Winograd F(4x4,3x3), 2 CTAs/SM for phase overlap.
//  - CTA = 32x16 px (32 tiles), 256 threads, smem 115200 B -> occupancy 2
//  - u layout [ic][q][oc][4] (conflict-free warp reads), 2 tiles/thread
//  - tag_kernel no-op shifts ncu -s 5 capture onto conv_kernel
// ---------------------------------------------------------------------------

#define HW (512 * 512)

__device__ float g_partial[1024];                       // (b*16+c)*4 + quarter
__device__ __align__(16) float g_u[16 * 16 * 9 * 64];   // [b][ic][q][oc][4]

// ------------------------------ 1) pooling --------------------------------
__global__ void pool_kernel(const float* __restrict__ x) {
    const int blk = blockIdx.x;
    const int bc  = blk >> 2;
    const int q   = blk & 3;
    const float4* p = reinterpret_cast<const float4*>(x + (size_t)bc * HW + (size_t)q * 65536);
    float s = 0.0f;
    #pragma unroll 4
    for (int i = threadIdx.x; i < 16384; i += 256) {
        float4 v = p[i];
        s += (v.x + v.y) + (v.z + v.w);
    }
    #pragma unroll
    for (int o = 16; o > 0; o >>= 1) s += __shfl_down_sync(0xffffffffu, s, o);
    __shared__ float ws[8];
    if ((threadIdx.x & 31) == 0) ws[threadIdx.x >> 5] = s;
    __syncthreads();
    if (threadIdx.x == 0) {
        float t = 0.0f;
        #pragma unroll
        for (int i = 0; i < 8; i++) t += ws[i];
        g_partial[blk] = t;
    }
}

// --------------- 2) routing softmax + Winograd weight transform -----------
__global__ void mix_kernel(const float* __restrict__ w_experts,
                           const float* __restrict__ fc_w,
                           const float* __restrict__ fc_b) {
    __shared__ float pooled_s[256];
    __shared__ float r_s[16][3];
    const int tid = threadIdx.x;

    pooled_s[tid] = (g_partial[tid * 4 + 0] + g_partial[tid * 4 + 1] +
                     g_partial[tid * 4 + 2] + g_partial[tid * 4 + 3]) * (1.0f / (float)HW);
    __syncthreads();

    if (tid < 16) {
        float lg[3];
        #pragma unroll
        for (int e = 0; e < 3; e++) {
            float a = fc_b[e];
            #pragma unroll
            for (int c = 0; c < 16; c++) a += pooled_s[tid * 16 + c] * fc_w[e * 16 + c];
            lg[e] = a;
        }
        float m = fmaxf(lg[0], fmaxf(lg[1], lg[2]));
        float ex0 = expf(lg[0] - m), ex1 = expf(lg[1] - m), ex2 = expf(lg[2] - m);
        float inv = 1.0f / (ex0 + ex1 + ex2);
        r_s[tid][0] = ex0 * inv;
        r_s[tid][1] = ex1 * inv;
        r_s[tid][2] = ex2 * inv;
    }
    __syncthreads();

    for (int job = tid; job < 4096; job += 256) {
        int b  = job >> 8;
        int ic = (job >> 4) & 15;
        int oc = job & 15;

        float w[3][3];
        #pragma unroll
        for (int r = 0; r < 3; r++)
            #pragma unroll
            for (int c = 0; c < 3; c++) {
                float v = 0.0f;
                #pragma unroll
                for (int e = 0; e < 3; e++)
                    v += r_s[b][e] * w_experts[((e * 16 + oc) * 16 + ic) * 9 + r * 3 + c];
                w[r][c] = v;
            }

        float T[6][3];
        #pragma unroll
        for (int c = 0; c < 3; c++) {
            float w0 = w[0][c], w1 = w[1][c], w2 = w[2][c];
            T[0][c] = 0.25f * w0;
            T[1][c] = (-1.0f / 6.0f) * (w0 + w1 + w2);
            T[2][c] = (1.0f / 6.0f) * (-w0 + w1 - w2);
            T[3][c] = (1.0f / 24.0f) * w0 + (1.0f / 12.0f) * w1 + (1.0f / 6.0f) * w2;
            T[4][c] = (1.0f / 24.0f) * w0 - (1.0f / 12.0f) * w1 + (1.0f / 6.0f) * w2;
            T[5][c] = w2;
        }
        float u36[36];
        #pragma unroll
        for (int i = 0; i < 6; i++) {
            float t0 = T[i][0], t1 = T[i][1], t2 = T[i][2];
            u36[i * 6 + 0] = 0.25f * t0;
            u36[i * 6 + 1] = (-1.0f / 6.0f) * (t0 + t1 + t2);
            u36[i * 6 + 2] = (1.0f / 6.0f) * (-t0 + t1 - t2);
            u36[i * 6 + 3] = (1.0f / 24.0f) * t0 + (1.0f / 12.0f) * t1 + (1.0f / 6.0f) * t2;
            u36[i * 6 + 4] = (1.0f / 24.0f) * t0 - (1.0f / 12.0f) * t1 + (1.0f / 6.0f) * t2;
            u36[i * 6 + 5] = t2;
        }
        float* base = g_u + (size_t)(b * 16 + ic) * 576 + oc * 4;
        #pragma unroll
        for (int q = 0; q < 9; q++) {
            base[q * 64 + 0] = u36[q * 4 + 0];
            base[q * 64 + 1] = u36[q * 4 + 1];
            base[q * 64 + 2] = u36[q * 4 + 2];
            base[q * 64 + 3] = u36[q * 4 + 3];
        }
    }
}

// ------- no-op: shifts ncu's -s 5 capture slot onto conv_kernel -----------
__global__ void tag_kernel() {}

// ------------------------- 3) Winograd conv -------------------------------
__device__ __forceinline__ void btrans(float v0, float v1, float v2, float v3,
                                       float v4, float v5,
                                       float& o0, float& o1, float& o2,
                                       float& o3, float& o4, float& o5) {
    float a = v1 + v2;
    float b = v3 + v4;
    float c = v1 - v2;
    float e = v4 - v3;
    float f = v3 - v1;
    float g = v4 - v2;
    o0 = fmaf(4.0f, v0, fmaf(-5.0f, v2, v4));
    o1 = fmaf(-4.0f, a, b);
    o2 = fmaf(4.0f, c, e);
    o3 = fmaf(2.0f, f, g);
    o4 = fmaf(-2.0f, f, g);
    o5 = fmaf(4.0f, v1, fmaf(-5.0f, v3, v5));
}

__device__ __forceinline__ void atrans(float v0, float v1, float v2, float v3,
                                       float v4, float v5,
                                       float& o0, float& o1, float& o2, float& o3) {
    float s1 = v1 + v2;
    float s2 = v1 - v2;
    float s3 = v3 + v4;
    float s4 = v3 - v4;
    o0 = v0 + s1 + s3;
    o1 = fmaf(2.0f, s4, s2);
    o2 = fmaf(4.0f, s3, s1);
    o3 = fmaf(8.0f, s4, s2) + v5;
}

// SMEM (floats):
//   bd_s  : [16 ic][32 tile][36] -> 18432  (offset 0)
//   union : 10368                 (offset 18432)
//       phases A/B: in_s [16 ic][18 rows][36 stride] (cols 0..33 used)
//       phase  C  : w_s  [16 ic][9 q][16 oc][4] = 9216
// total 28800 floats = 115200 bytes -> 2 CTAs/SM
__global__ void __launch_bounds__(256, 2)
conv_kernel(const float* __restrict__ x, const float* __restrict__ bias,
            float* __restrict__ out) {
    extern __shared__ float smem[];
    float* bd_s = smem;
    float* un_s = smem + 18432;      // in_s during A/B, w_s during C

    const int tid = threadIdx.x;
    const int b   = blockIdx.z;
    const int x0  = blockIdx.x * 32;
    const int y0  = blockIdx.y * 16;

    const int oc  = tid & 15;
    const int grp = tid >> 4;        // 0..15 -> tiles 2*grp, 2*grp+1

    const float bv = bias[oc];
    const float* xb = x + (size_t)b * 16 * HW;

    // ---- phase A: input tile 16ic x 18 x 34 (reflect halo), stride 36 ----
    for (int i = tid; i < 9792; i += 256) {
        int c   = i / 612;                   // 18*34
        int rem = i - c * 612;
        int row = rem / 34;
        int col = rem - row * 34;
        int gy = y0 + row - 1; gy = gy < 0 ? -gy : (gy > 511 ? 1022 - gy : gy);
        int gx = x0 + col - 1; gx = gx < 0 ? -gx : (gx > 511 ? 1022 - gx : gx);
        un_s[c * 648 + row * 36 + col] = xb[(c << 18) + (gy << 9) + gx];
    }
    __syncthreads();

    // ---- phase B: input transform, 2 jobs/thread (16ic x 32 tiles) ----
    #pragma unroll
    for (int s = 0; s < 2; s++) {
        const int job  = tid + s * 256;
        const int b_ic = job >> 5;
        const int b_t  = job & 31;
        const int b_tx = b_t & 7;
        const int b_ty = b_t >> 3;
        const float* p = un_s + b_ic * 648 + (4 * b_ty) * 36 + 4 * b_tx;

        float d[6][6];
        #pragma unroll
        for (int r = 0; r < 6; r++) {
            float4 a  = *reinterpret_cast<const float4*>(p + r * 36);
            float2 b2 = *reinterpret_cast<const float2*>(p + r * 36 + 4);
            d[r][0] = a.x; d[r][1] = a.y; d[r][2] = a.z; d[r][3] = a.w;
            d[r][4] = b2.x; d[r][5] = b2.y;
        }
        float t[6][6];
        #pragma unroll
        for (int c = 0; c < 6; c++)
            btrans(d[0][c], d[1][c], d[2][c], d[3][c], d[4][c], d[5][c],
                   t[0][c], t[1][c], t[2][c], t[3][c], t[4][c], t[5][c]);
        float bd[36];
        #pragma unroll
        for (int i = 0; i < 6; i++)
            btrans(t[i][0], t[i][1], t[i][2], t[i][3], t[i][4], t[i][5],
                   bd[i * 6 + 0], bd[i * 6 + 1], bd[i * 6 + 2],
                   bd[i * 6 + 3], bd[i * 6 + 4], bd[i * 6 + 5]);

        float* dst = bd_s + (b_ic * 32 + b_t) * 36;
        #pragma unroll
        for (int q = 0; q < 9; q++)
            *reinterpret_cast<float4*>(dst + q * 4) =
                make_float4(bd[q * 4 + 0], bd[q * 4 + 1], bd[q * 4 + 2], bd[q * 4 + 3]);
    }
    __syncthreads();

    // ---- load transformed weights into union (in_s dead now) ----
    {
        const float4* src = reinterpret_cast<const float4*>(g_u + (size_t)b * 9216);
        float4* dst = reinterpret_cast<float4*>(un_s);
        #pragma unroll
        for (int k = 0; k < 9; k++) {
            int i = tid + k * 256;
            if (i < 2304) dst[i] = src[i];
        }
    }
    __syncthreads();

    // ---- phase C: accumulate m[2][36] over 16 ic ----
    float m0[36], m1[36];
    #pragma unroll
    for (int j = 0; j < 36; j++) { m0[j] = 0.0f; m1[j] = 0.0f; }
    {
        const float* bdp0 = bd_s + (grp * 2 + 0) * 36;
        const float* bdp1 = bd_s + (grp * 2 + 1) * 36;
        const float* wq   = un_s + oc * 4;
        #pragma unroll 1
        for (int ic = 0; ic < 16; ic++) {
            #pragma unroll
            for (int q = 0; q < 9; q++) {
                float4 u  = *reinterpret_cast<const float4*>(wq + q * 64);
                float4 b0 = *reinterpret_cast<const float4*>(bdp0 + q * 4);
                float4 b1 = *reinterpret_cast<const float4*>(bdp1 + q * 4);
                m0[q*4+0] = fmaf(b0.x, u.x, m0[q*4+0]);
                m0[q*4+1] = fmaf(b0.y, u.y, m0[q*4+1]);
                m0[q*4+2] = fmaf(b0.z, u.z, m0[q*4+2]);
                m0[q*4+3] = fmaf(b0.w, u.w, m0[q*4+3]);
                m1[q*4+0] = fmaf(b1.x, u.x, m1[q*4+0]);
                m1[q*4+1] = fmaf(b1.y, u.y, m1[q*4+1]);
                m1[q*4+2] = fmaf(b1.z, u.z, m1[q*4+2]);
                m1[q*4+3] = fmaf(b1.w, u.w, m1[q*4+3]);
            }
            bdp0 += 32 * 36;
            bdp1 += 32 * 36;
            wq   += 576;
        }
    }

    // ---- phase D: A^T m A + bias for both tiles ----
    #pragma unroll
    for (int t2 = 0; t2 < 2; t2++) {
        const float* m = t2 ? m1 : m0;
        const int tile = grp * 2 + t2;
        const int tx = tile & 7;
        const int ty = tile >> 3;

        float t[4][6];
        #pragma unroll
        for (int j = 0; j < 6; j++)
            atrans(m[0 * 6 + j], m[1 * 6 + j], m[2 * 6 + j],
                   m[3 * 6 + j], m[4 * 6 + j], m[5 * 6 + j],
                   t[0][j], t[1][j], t[2][j], t[3][j]);

        float* op = out + ((size_t)(b * 16 + oc) << 18) +
                    ((size_t)(y0 + 4 * ty) << 9) + (x0 + 4 * tx);
        #pragma unroll
        for (int r = 0; r < 4; r++) {
            float o0, o1, o2, o3;
            atrans(t[r][0], t[r][1], t[r][2], t[r][3], t[r][4], t[r][5],
                   o0, o1, o2, o3);
            *reinterpret_cast<float4*>(op + ((size_t)r << 9)) =
                make_float4(o0 + bv, o1 + bv, o2 + bv, o3 + bv);
        }
    }
}

// ---------------------------------------------------------------------------
extern "C" void kernel_launch(void* const* d_in, const int* in_sizes, int n_in,
                              void* d_out, int out_size) {
    const float* x         = (const float*)d_in[0];
    const float* w_experts = (const float*)d_in[1];
    const float* bias      = (const float*)d_in[2];
    const float* fc_w      = (const float*)d_in[3];
    const float* fc_b      = (const float*)d_in[4];
    float* out = (float*)d_out;

    const int smem_bytes = 28800 * 4;   // 115200
    cudaFuncSetAttribute(conv_kernel, cudaFuncAttributeMaxDynamicSharedMemorySize, smem_bytes);

    pool_kernel<<<1024, 256>>>(x);
    mix_kernel<<<1, 256>>>(w_experts, fc_w, fc_b);
    tag_kernel<<<1, 32>>>();
    conv_kernel<<<dim3(16, 32, 16), 256, smem_bytes>>>(x, bias, out);
}

// round 10
// speedup vs baseline: 1.8637x; 1.0346x over previous
#include <cuda_runtime.h>

// ---------------------------------------------------------------------------
// DyNet2D R9: Winograd F(4x4,3x3). R7 + streaming phase-B transform to
// eliminate register spills (phase B peak was ~110 regs -> 128 cap -> LDL/STL
// traffic dominating L1 at 78%).
// ---------------------------------------------------------------------------

#define HW (512 * 512)

__device__ float g_partial[1024];                       // (b*16+c)*4 + quarter
__device__ __align__(16) float g_u[16 * 16 * 9 * 64];   // [b][ic][q][oc][4]

// ------------------------------ 1) pooling --------------------------------
__global__ void pool_kernel(const float* __restrict__ x) {
    const int blk = blockIdx.x;
    const int bc  = blk >> 2;
    const int q   = blk & 3;
    const float4* p = reinterpret_cast<const float4*>(x + (size_t)bc * HW + (size_t)q * 65536);
    float s = 0.0f;
    #pragma unroll 4
    for (int i = threadIdx.x; i < 16384; i += 256) {
        float4 v = p[i];
        s += (v.x + v.y) + (v.z + v.w);
    }
    #pragma unroll
    for (int o = 16; o > 0; o >>= 1) s += __shfl_down_sync(0xffffffffu, s, o);
    __shared__ float ws[8];
    if ((threadIdx.x & 31) == 0) ws[threadIdx.x >> 5] = s;
    __syncthreads();
    if (threadIdx.x == 0) {
        float t = 0.0f;
        #pragma unroll
        for (int i = 0; i < 8; i++) t += ws[i];
        g_partial[blk] = t;
    }
}

// --------------- 2) routing softmax + Winograd weight transform -----------
__global__ void mix_kernel(const float* __restrict__ w_experts,
                           const float* __restrict__ fc_w,
                           const float* __restrict__ fc_b) {
    __shared__ float pooled_s[256];
    __shared__ float r_s[16][3];
    const int tid = threadIdx.x;

    pooled_s[tid] = (g_partial[tid * 4 + 0] + g_partial[tid * 4 + 1] +
                     g_partial[tid * 4 + 2] + g_partial[tid * 4 + 3]) * (1.0f / (float)HW);
    __syncthreads();

    if (tid < 16) {
        float lg[3];
        #pragma unroll
        for (int e = 0; e < 3; e++) {
            float a = fc_b[e];
            #pragma unroll
            for (int c = 0; c < 16; c++) a += pooled_s[tid * 16 + c] * fc_w[e * 16 + c];
            lg[e] = a;
        }
        float m = fmaxf(lg[0], fmaxf(lg[1], lg[2]));
        float ex0 = expf(lg[0] - m), ex1 = expf(lg[1] - m), ex2 = expf(lg[2] - m);
        float inv = 1.0f / (ex0 + ex1 + ex2);
        r_s[tid][0] = ex0 * inv;
        r_s[tid][1] = ex1 * inv;
        r_s[tid][2] = ex2 * inv;
    }
    __syncthreads();

    for (int job = tid; job < 4096; job += 256) {
        int b  = job >> 8;
        int ic = (job >> 4) & 15;
        int oc = job & 15;

        float w[3][3];
        #pragma unroll
        for (int r = 0; r < 3; r++)
            #pragma unroll
            for (int c = 0; c < 3; c++) {
                float v = 0.0f;
                #pragma unroll
                for (int e = 0; e < 3; e++)
                    v += r_s[b][e] * w_experts[((e * 16 + oc) * 16 + ic) * 9 + r * 3 + c];
                w[r][c] = v;
            }

        float T[6][3];
        #pragma unroll
        for (int c = 0; c < 3; c++) {
            float w0 = w[0][c], w1 = w[1][c], w2 = w[2][c];
            T[0][c] = 0.25f * w0;
            T[1][c] = (-1.0f / 6.0f) * (w0 + w1 + w2);
            T[2][c] = (1.0f / 6.0f) * (-w0 + w1 - w2);
            T[3][c] = (1.0f / 24.0f) * w0 + (1.0f / 12.0f) * w1 + (1.0f / 6.0f) * w2;
            T[4][c] = (1.0f / 24.0f) * w0 - (1.0f / 12.0f) * w1 + (1.0f / 6.0f) * w2;
            T[5][c] = w2;
        }
        float u36[36];
        #pragma unroll
        for (int i = 0; i < 6; i++) {
            float t0 = T[i][0], t1 = T[i][1], t2 = T[i][2];
            u36[i * 6 + 0] = 0.25f * t0;
            u36[i * 6 + 1] = (-1.0f / 6.0f) * (t0 + t1 + t2);
            u36[i * 6 + 2] = (1.0f / 6.0f) * (-t0 + t1 - t2);
            u36[i * 6 + 3] = (1.0f / 24.0f) * t0 + (1.0f / 12.0f) * t1 + (1.0f / 6.0f) * t2;
            u36[i * 6 + 4] = (1.0f / 24.0f) * t0 - (1.0f / 12.0f) * t1 + (1.0f / 6.0f) * t2;
            u36[i * 6 + 5] = t2;
        }
        float* base = g_u + (size_t)(b * 16 + ic) * 576 + oc * 4;
        #pragma unroll
        for (int q = 0; q < 9; q++) {
            base[q * 64 + 0] = u36[q * 4 + 0];
            base[q * 64 + 1] = u36[q * 4 + 1];
            base[q * 64 + 2] = u36[q * 4 + 2];
            base[q * 64 + 3] = u36[q * 4 + 3];
        }
    }
}

// ------- no-op: shifts ncu's -s 5 capture slot onto conv_kernel -----------
__global__ void tag_kernel() {}

// ------------------------- 3) Winograd conv -------------------------------
__device__ __forceinline__ void btrans(float v0, float v1, float v2, float v3,
                                       float v4, float v5,
                                       float& o0, float& o1, float& o2,
                                       float& o3, float& o4, float& o5) {
    float a = v1 + v2;
    float b = v3 + v4;
    float c = v1 - v2;
    float e = v4 - v3;
    float f = v3 - v1;
    float g = v4 - v2;
    o0 = fmaf(4.0f, v0, fmaf(-5.0f, v2, v4));
    o1 = fmaf(-4.0f, a, b);
    o2 = fmaf(4.0f, c, e);
    o3 = fmaf(2.0f, f, g);
    o4 = fmaf(-2.0f, f, g);
    o5 = fmaf(4.0f, v1, fmaf(-5.0f, v3, v5));
}

__device__ __forceinline__ void atrans(float v0, float v1, float v2, float v3,
                                       float v4, float v5,
                                       float& o0, float& o1, float& o2, float& o3) {
    float s1 = v1 + v2;
    float s2 = v1 - v2;
    float s3 = v3 + v4;
    float s4 = v3 - v4;
    o0 = v0 + s1 + s3;
    o1 = fmaf(2.0f, s4, s2);
    o2 = fmaf(4.0f, s3, s1);
    o3 = fmaf(8.0f, s4, s2) + v5;
}

// SMEM (floats):
//   bd_s  : [16 ic][32 tile][36] -> 18432  (offset 0)
//   union : 10368                 (offset 18432)
//       phases A/B: in_s [16 ic][18 rows][36 stride] (cols 0..33 used)
//       phase  C  : w_s  [16 ic][9 q][16 oc][4] = 9216
// total 28800 floats = 115200 bytes -> 2 CTAs/SM
__global__ void __launch_bounds__(256, 2)
conv_kernel(const float* __restrict__ x, const float* __restrict__ bias,
            float* __restrict__ out) {
    extern __shared__ float smem[];
    float* bd_s = smem;
    float* un_s = smem + 18432;      // in_s during A/B, w_s during C

    const int tid = threadIdx.x;
    const int b   = blockIdx.z;
    const int x0  = blockIdx.x * 32;
    const int y0  = blockIdx.y * 16;

    const int oc  = tid & 15;
    const int grp = tid >> 4;        // 0..15 -> tiles 2*grp, 2*grp+1

    const float bv = bias[oc];
    const float* xb = x + (size_t)b * 16 * HW;

    // ---- phase A: input tile 16ic x 18 x 34 (reflect halo), stride 36 ----
    for (int i = tid; i < 9792; i += 256) {
        int c   = i / 612;                   // 18*34
        int rem = i - c * 612;
        int row = rem / 34;
        int col = rem - row * 34;
        int gy = y0 + row - 1; gy = gy < 0 ? -gy : (gy > 511 ? 1022 - gy : gy);
        int gx = x0 + col - 1; gx = gx < 0 ? -gx : (gx > 511 ? 1022 - gx : gx);
        un_s[c * 648 + row * 36 + col] = xb[(c << 18) + (gy << 9) + gx];
    }
    __syncthreads();

    // ---- phase B: streaming input transform, 2 jobs/thread ----
    // Pass 1 streams d column-by-column (6 live d regs); pass 2 streams bd
    // row-by-row straight to SMEM (6 live). Peak live set = t[36] + ~10.
    #pragma unroll 1
    for (int s = 0; s < 2; s++) {
        const int job  = tid + s * 256;
        const int b_ic = job >> 5;
        const int b_t  = job & 31;
        const int b_tx = b_t & 7;
        const int b_ty = b_t >> 3;
        const float* p = un_s + b_ic * 648 + (4 * b_ty) * 36 + 4 * b_tx;

        float t[6][6];
        #pragma unroll
        for (int c = 0; c < 6; c++) {
            float d0 = p[0 * 36 + c];
            float d1 = p[1 * 36 + c];
            float d2 = p[2 * 36 + c];
            float d3 = p[3 * 36 + c];
            float d4 = p[4 * 36 + c];
            float d5 = p[5 * 36 + c];
            btrans(d0, d1, d2, d3, d4, d5,
                   t[0][c], t[1][c], t[2][c], t[3][c], t[4][c], t[5][c]);
        }
        float* dst = bd_s + (b_ic * 32 + b_t) * 36;
        #pragma unroll
        for (int i = 0; i < 6; i++) {
            float o0, o1, o2, o3, o4, o5;
            btrans(t[i][0], t[i][1], t[i][2], t[i][3], t[i][4], t[i][5],
                   o0, o1, o2, o3, o4, o5);
            dst[i * 6 + 0] = o0;
            dst[i * 6 + 1] = o1;
            dst[i * 6 + 2] = o2;
            dst[i * 6 + 3] = o3;
            dst[i * 6 + 4] = o4;
            dst[i * 6 + 5] = o5;
        }
    }
    __syncthreads();

    // ---- load transformed weights into union (in_s dead now) ----
    {
        const float4* src = reinterpret_cast<const float4*>(g_u + (size_t)b * 9216);
        float4* dst = reinterpret_cast<float4*>(un_s);
        #pragma unroll
        for (int k = 0; k < 9; k++) {
            int i = tid + k * 256;
            if (i < 2304) dst[i] = src[i];
        }
    }
    __syncthreads();

    // ---- phase C: accumulate m[2][36] over 16 ic ----
    float m0[36], m1[36];
    #pragma unroll
    for (int j = 0; j < 36; j++) { m0[j] = 0.0f; m1[j] = 0.0f; }
    {
        const float* bdp0 = bd_s + (grp * 2 + 0) * 36;
        const float* bdp1 = bd_s + (grp * 2 + 1) * 36;
        const float* wq   = un_s + oc * 4;
        #pragma unroll 1
        for (int ic = 0; ic < 16; ic++) {
            #pragma unroll
            for (int q = 0; q < 9; q++) {
                float4 u  = *reinterpret_cast<const float4*>(wq + q * 64);
                float4 b0 = *reinterpret_cast<const float4*>(bdp0 + q * 4);
                float4 b1 = *reinterpret_cast<const float4*>(bdp1 + q * 4);
                m0[q*4+0] = fmaf(b0.x, u.x, m0[q*4+0]);
                m0[q*4+1] = fmaf(b0.y, u.y, m0[q*4+1]);
                m0[q*4+2] = fmaf(b0.z, u.z, m0[q*4+2]);
                m0[q*4+3] = fmaf(b0.w, u.w, m0[q*4+3]);
                m1[q*4+0] = fmaf(b1.x, u.x, m1[q*4+0]);
                m1[q*4+1] = fmaf(b1.y, u.y, m1[q*4+1]);
                m1[q*4+2] = fmaf(b1.z, u.z, m1[q*4+2]);
                m1[q*4+3] = fmaf(b1.w, u.w, m1[q*4+3]);
            }
            bdp0 += 32 * 36;
            bdp1 += 32 * 36;
            wq   += 576;
        }
    }

    // ---- phase D: A^T m A + bias for both tiles ----
    #pragma unroll
    for (int t2 = 0; t2 < 2; t2++) {
        const float* m = t2 ? m1 : m0;
        const int tile = grp * 2 + t2;
        const int tx = tile & 7;
        const int ty = tile >> 3;

        float t[4][6];
        #pragma unroll
        for (int j = 0; j < 6; j++)
            atrans(m[0 * 6 + j], m[1 * 6 + j], m[2 * 6 + j],
                   m[3 * 6 + j], m[4 * 6 + j], m[5 * 6 + j],
                   t[0][j], t[1][j], t[2][j], t[3][j]);

        float* op = out + ((size_t)(b * 16 + oc) << 18) +
                    ((size_t)(y0 + 4 * ty) << 9) + (x0 + 4 * tx);
        #pragma unroll
        for (int r = 0; r < 4; r++) {
            float o0, o1, o2, o3;
            atrans(t[r][0], t[r][1], t[r][2], t[r][3], t[r][4], t[r][5],
                   o0, o1, o2, o3);
            *reinterpret_cast<float4*>(op + ((size_t)r << 9)) =
                make_float4(o0 + bv, o1 + bv, o2 + bv, o3 + bv);
        }
    }
}

// ---------------------------------------------------------------------------
extern "C" void kernel_launch(void* const* d_in, const int* in_sizes, int n_in,
                              void* d_out, int out_size) {
    const float* x         = (const float*)d_in[0];
    const float* w_experts = (const float*)d_in[1];
    const float* bias      = (const float*)d_in[2];
    const float* fc_w      = (const float*)d_in[3];
    const float* fc_b      = (const float*)d_in[4];
    float* out = (float*)d_out;

    const int smem_bytes = 28800 * 4;   // 115200
    cudaFuncSetAttribute(conv_kernel, cudaFuncAttributeMaxDynamicSharedMemorySize, smem_bytes);

    pool_kernel<<<1024, 256>>>(x);
    mix_kernel<<<1, 256>>>(w_experts, fc_w, fc_b);
    tag_kernel<<<1, 32>>>();
    conv_kernel<<<dim3(16, 32, 16), 256, smem_bytes>>>(x, bias, out);
}